// round 1
// baseline (speedup 1.0000x reference)
#include <cuda_runtime.h>

// ---------------------------------------------------------------------------
// Device-global accumulators (no allocation allowed). g_accum[0] = img CE sum,
// g_accum[1] = cls CE sum. Zeroed at the start of every launch sequence.
// ---------------------------------------------------------------------------
__device__ double g_accum[2];

__global__ void zero_accum_kernel() {
    g_accum[0] = 0.0;
    g_accum[1] = 0.0;
}

// ---------------------------------------------------------------------------
// JAX threefry-2x32 block cipher (exact port of jax/_src/prng.py).
// key = (k0, k1); input words (x0, x1); 20 rounds, 5 key injections.
// ---------------------------------------------------------------------------
__device__ __forceinline__ void threefry2x32(unsigned k0, unsigned k1,
                                             unsigned x0, unsigned x1,
                                             unsigned& o0, unsigned& o1) {
    const unsigned ks2 = k0 ^ k1 ^ 0x1BD11BDAu;
    x0 += k0; x1 += k1;
#define TF_RND(R) { x0 += x1; x1 = __funnelshift_l(x1, x1, (R)); x1 ^= x0; }
    TF_RND(13) TF_RND(15) TF_RND(26) TF_RND(6)
    x0 += k1;  x1 += ks2 + 1u;
    TF_RND(17) TF_RND(29) TF_RND(16) TF_RND(24)
    x0 += ks2; x1 += k0 + 2u;
    TF_RND(13) TF_RND(15) TF_RND(26) TF_RND(6)
    x0 += k0;  x1 += k1 + 3u;
    TF_RND(17) TF_RND(29) TF_RND(16) TF_RND(24)
    x0 += k1;  x1 += ks2 + 4u;
    TF_RND(13) TF_RND(15) TF_RND(26) TF_RND(6)
    x0 += ks2; x1 += k0 + 5u;
#undef TF_RND
    o0 = x0; o1 = x1;
}

// ---------------------------------------------------------------------------
// XLA ErfInv f32 (Giles polynomial) — matches lax.erf_inv on GPU.
// ---------------------------------------------------------------------------
__device__ __forceinline__ float erfinv_xla(float x) {
    float w = -__logf(fmaf(-x, x, 1.0f));
    float p;
    if (w < 5.0f) {
        w = w - 2.5f;
        p =            2.81022636e-08f;
        p = fmaf(p, w, 3.43273939e-07f);
        p = fmaf(p, w, -3.5233877e-06f);
        p = fmaf(p, w, -4.39150654e-06f);
        p = fmaf(p, w, 0.00021858087f);
        p = fmaf(p, w, -0.00125372503f);
        p = fmaf(p, w, -0.00417768164f);
        p = fmaf(p, w, 0.246640727f);
        p = fmaf(p, w, 1.50140941f);
    } else {
        w = sqrtf(w) - 3.0f;
        p =            -0.000200214257f;
        p = fmaf(p, w, 0.000100950558f);
        p = fmaf(p, w, 0.00134934322f);
        p = fmaf(p, w, -0.00367342844f);
        p = fmaf(p, w, 0.00573950773f);
        p = fmaf(p, w, -0.0076224613f);
        p = fmaf(p, w, 0.00943887047f);
        p = fmaf(p, w, 1.00167406f);
        p = fmaf(p, w, 2.83297682f);
    }
    return p * x;
}

// jax.random.normal: uniform(lo=nextafter(-1,0), hi=1) -> sqrt(2)*erfinv(u)
__device__ __forceinline__ float bits_to_normal(unsigned b) {
    // u01 in [0,1): mantissa trick, matches XLA exactly
    float u01 = __uint_as_float((b >> 9) | 0x3f800000u) - 1.0f;
    // u = u01*(hi-lo)+lo; hi-lo = 1.9999999404, lo = -0.99999994039535522
    float x = fmaf(u01, 1.9999999403953552f, -0.99999994039535522f);
    x = fmaxf(x, -0.99999994039535522f);
    return 1.4142135381698608f * erfinv_xla(x);
}

// CE for one MC sample: -sum_c true_c * log_softmax(noisy)_c
__device__ __forceinline__ float ce3(float l0, float l1, float l2, float s,
                                     float e0, float e1, float e2,
                                     float t0, float t1, float t2, float ts) {
    float n0 = fmaf(e0, s, l0);
    float n1 = fmaf(e1, s, l1);
    float n2 = fmaf(e2, s, l2);
    float m  = fmaxf(n0, fmaxf(n1, n2));
    float s0 = n0 - m, s1 = n1 - m, s2 = n2 - m;
    float Z  = __expf(s0) + __expf(s1) + __expf(s2);
    float lZ = __logf(Z);
    return ts * lZ - (t0 * s0 + t1 * s1 + t2 * s2);
}

// ---------------------------------------------------------------------------
// Main MC kernel. One thread handles pixel n and TT consecutive t values in
// [0,250); each cipher yields eps for (t,n,c) AND (t+250,n,c) (the two iota
// halves), so both CE samples are computed per cipher triple.
//   bits index: idx(t,n,c) = (t*N + n)*3 + c ; half = N*750
// ---------------------------------------------------------------------------
template <int TT>
__global__ void mc_loss_kernel(const float* __restrict__ tru,
                               const float4* __restrict__ pred,
                               int N, unsigned k0, unsigned k1, int accIdx) {
    const int chunks = 250 / TT;
    int tid = blockIdx.x * blockDim.x + threadIdx.x;
    float local = 0.0f;
    int total = N * chunks;
    if (tid < total) {
        int n  = tid / chunks;
        int tb = (tid - n * chunks) * TT;

        float4 p = pred[n];
        float l0 = p.x, l1 = p.y, l2 = p.z;
        float scale = sqrtf(__expf(p.w));   // sqrt(exp(log_var))
        float t0 = tru[3 * n + 0];
        float t1 = tru[3 * n + 1];
        float t2 = tru[3 * n + 2];
        float ts = t0 + t1 + t2;

        const unsigned half = (unsigned)N * 750u;
        unsigned base = ((unsigned)tb * (unsigned)N + (unsigned)n) * 3u;
        const unsigned stride = (unsigned)N * 3u;

#pragma unroll
        for (int k = 0; k < TT; k++) {
            float eA[3], eB[3];
#pragma unroll
            for (int c = 0; c < 3; c++) {
                unsigned b0, b1;
                threefry2x32(k0, k1, base + (unsigned)c, half + base + (unsigned)c, b0, b1);
                eA[c] = bits_to_normal(b0);
                eB[c] = bits_to_normal(b1);
            }
            local += ce3(l0, l1, l2, scale, eA[0], eA[1], eA[2], t0, t1, t2, ts);
            local += ce3(l0, l1, l2, scale, eB[0], eB[1], eB[2], t0, t1, t2, ts);
            base += stride;
        }
    }

    // Block reduction: warp shuffle -> shared -> one double atomic per block
#pragma unroll
    for (int o = 16; o > 0; o >>= 1)
        local += __shfl_down_sync(0xffffffffu, local, o);

    __shared__ float warpsum[32];
    int lane = threadIdx.x & 31;
    int w    = threadIdx.x >> 5;
    if (lane == 0) warpsum[w] = local;
    __syncthreads();
    if (w == 0) {
        int nw = (blockDim.x + 31) >> 5;
        float v = (lane < nw) ? warpsum[lane] : 0.0f;
#pragma unroll
        for (int o = 16; o > 0; o >>= 1)
            v += __shfl_down_sync(0xffffffffu, v, o);
        if (lane == 0) atomicAdd(&g_accum[accIdx], (double)v);
    }
}

// ---------------------------------------------------------------------------
// Finalize: scale sums to mc_loss, apply mean(weights), combine with log_vars.
// ---------------------------------------------------------------------------
__global__ void finalize_kernel(const float* __restrict__ log_vars,
                                const float* __restrict__ w_img,
                                const float* __restrict__ w_cls,
                                float* __restrict__ out,
                                double invImg, double invCls) {
    float mwi = (w_img[0] + w_img[1] + w_img[2]) * (1.0f / 3.0f);
    float mwc = (w_cls[0] + w_cls[1] + w_cls[2]) * (1.0f / 3.0f);
    float li = (float)(g_accum[0] * invImg) * mwi;
    float lc = (float)(g_accum[1] * invCls) * mwc;
    float lv0 = log_vars[0], lv1 = log_vars[1];
    out[0] = expf(-lv0) * li + lv0 + expf(-lv1) * lc + lv1;
}

// ---------------------------------------------------------------------------
// kernel_launch
// Inputs: 0=true_img(65536*3) 1=pred_img(65536*4) 2=true_cls(4*3)
//         3=pred_cls(4*4) 4=log_vars(2) 5=w_img(3) 6=w_cls(3)
// ---------------------------------------------------------------------------
extern "C" void kernel_launch(void* const* d_in, const int* in_sizes, int n_in,
                              void* d_out, int out_size) {
    (void)n_in; (void)out_size;
    const float* true_img = (const float*)d_in[0];
    const float* pred_img = (const float*)d_in[1];
    const float* true_cls = (const float*)d_in[2];
    const float* pred_cls = (const float*)d_in[3];
    const float* log_vars = (const float*)d_in[4];
    const float* w_img    = (const float*)d_in[5];
    const float* w_cls    = (const float*)d_in[6];

    int Nimg = in_sizes[1] / 4;   // 65536 pixels (pred has C+1=4 per row)
    int Ncls = in_sizes[3] / 4;   // 4 rows

    zero_accum_kernel<<<1, 1>>>();

    {   // img: key(123) -> (0,123); TT=5 -> 50 chunks per pixel
        int threads = Nimg * 50;
        int blocks  = (threads + 255) / 256;
        mc_loss_kernel<5><<<blocks, 256>>>(true_img, (const float4*)pred_img,
                                           Nimg, 0u, 123u, 0);
    }
    {   // cls: key(456) -> (0,456); TT=1 -> 250 chunks per row (1000 tasks)
        int threads = Ncls * 250;
        int blocks  = (threads + 255) / 256;
        mc_loss_kernel<1><<<blocks, 256>>>(true_cls, (const float4*)pred_cls,
                                           Ncls, 0u, 456u, 1);
    }

    finalize_kernel<<<1, 1>>>(log_vars, w_img, w_cls, (float*)d_out,
                              1.0 / (500.0 * (double)Nimg),
                              1.0 / (500.0 * (double)Ncls));
}

// round 3
// speedup vs baseline: 1.9712x; 1.9712x over previous
#include <cuda_runtime.h>

// ---------------------------------------------------------------------------
// Device-global state (zero-initialized at module load; finalizing block
// resets it every launch, so the invariant holds across graph replays).
// ---------------------------------------------------------------------------
__device__ double   g_accum[2];   // [0]=img CE sum, [1]=cls CE sum
__device__ unsigned g_done;       // block completion ticket counter

typedef unsigned long long u64;

// ---------------------------------------------------------------------------
// Packed f32x2 helpers (sm_103a): one instruction operates on 2 floats.
// ---------------------------------------------------------------------------
__device__ __forceinline__ u64 pk(float lo, float hi) {
    u64 r; asm("mov.b64 %0,{%1,%2};" : "=l"(r) : "f"(lo), "f"(hi)); return r;
}
__device__ __forceinline__ void upk(u64 v, float& lo, float& hi) {
    asm("mov.b64 {%0,%1},%2;" : "=f"(lo), "=f"(hi) : "l"(v));
}
__device__ __forceinline__ u64 fma2(u64 a, u64 b, u64 c) {
    u64 d; asm("fma.rn.f32x2 %0,%1,%2,%3;" : "=l"(d) : "l"(a), "l"(b), "l"(c)); return d;
}
__device__ __forceinline__ u64 mul2(u64 a, u64 b) {
    u64 d; asm("mul.rn.f32x2 %0,%1,%2;" : "=l"(d) : "l"(a), "l"(b)); return d;
}
__device__ __forceinline__ u64 add2(u64 a, u64 b) {
    u64 d; asm("add.rn.f32x2 %0,%1,%2;" : "=l"(d) : "l"(a), "l"(b)); return d;
}
__device__ __forceinline__ float lg2f(float x) {
    float y; asm("lg2.approx.f32 %0,%1;" : "=f"(y) : "f"(x)); return y;
}
__device__ __forceinline__ float ex2f(float x) {
    float y; asm("ex2.approx.f32 %0,%1;" : "=f"(y) : "f"(x)); return y;
}

// ---------------------------------------------------------------------------
// JAX threefry-2x32 specialized for key = (0, k1)  (jax.random.key(seed) with
// seed < 2^32 gives k0 = 0).  ks2 = k1 ^ 0x1BD11BDA.
// ---------------------------------------------------------------------------
__device__ __forceinline__ void tf2x32_k0(unsigned k1, unsigned ks2,
                                          unsigned k1p3, unsigned ks2p1, unsigned ks2p4,
                                          unsigned x0, unsigned x1,
                                          unsigned& o0, unsigned& o1) {
    /* x0 += 0 */ x1 += k1;
#define TF_RND(R) { x0 += x1; x1 = __funnelshift_l(x1, x1, (R)); x1 ^= x0; }
    TF_RND(13) TF_RND(15) TF_RND(26) TF_RND(6)
    x0 += k1;  x1 += ks2p1;
    TF_RND(17) TF_RND(29) TF_RND(16) TF_RND(24)
    x0 += ks2; x1 += 2u;
    TF_RND(13) TF_RND(15) TF_RND(26) TF_RND(6)
    /* x0 += 0 */ x1 += k1p3;
    TF_RND(17) TF_RND(29) TF_RND(16) TF_RND(24)
    x0 += k1;  x1 += ks2p4;
    TF_RND(13) TF_RND(15) TF_RND(26) TF_RND(6)
    x0 += ks2; x1 += 5u;
#undef TF_RND
    o0 = x0; o1 = x1;
}

// Tail branch of XLA erf_inv (w >= 5), returns p(w); probability 0.34%.
__device__ __forceinline__ float erfinv_tail(float wp /* = w - 2.5 */) {
    float w = wp + 2.5f;
    float v = sqrtf(w) - 3.0f;
    float p =            -0.000200214257f;
    p = fmaf(p, v, 0.000100950558f);
    p = fmaf(p, v, 0.00134934322f);
    p = fmaf(p, v, -0.00367342844f);
    p = fmaf(p, v, 0.00573950773f);
    p = fmaf(p, v, -0.0076224613f);
    p = fmaf(p, v, 0.00943887047f);
    p = fmaf(p, v, 1.00167406f);
    p = fmaf(p, v, 2.83297682f);
    return p;
}

// bits -> x in [lo, 1): XLA uniform mantissa trick + affine + clamp.
__device__ __forceinline__ float bits_to_x(unsigned b) {
    float u01 = __uint_as_float((b >> 9) | 0x3f800000u) - 1.0f;
    float x = fmaf(u01, 1.9999999403953552f, -0.99999994039535522f);
    return fmaxf(x, -0.99999994039535522f);
}

// ---------------------------------------------------------------------------
// MC worker. One thread: pixel n, TT consecutive t-pairs (t, t+250).
// Returns this thread's CE contribution (already summed over its samples).
// ---------------------------------------------------------------------------
__device__ float mc_work(const float* __restrict__ tru,
                         const float4* __restrict__ pred,
                         int N, int TT, int chunks, int tid, unsigned k1) {
    int total = N * chunks;
    if (tid >= total) return 0.0f;

    const unsigned ks2   = k1 ^ 0x1BD11BDAu;
    const unsigned k1p3  = k1 + 3u;
    const unsigned ks2p1 = ks2 + 1u;
    const unsigned ks2p4 = ks2 + 4u;

    int n  = tid / chunks;
    int tb = (tid - n * chunks) * TT;

    float4 p = pred[n];
    float l0 = p.x, l1 = p.y, l2 = p.z;
    float scale = sqrtf(__expf(p.w));
    float s2 = 1.41421356237f * scale;            // sqrt(2) * scale
    float t0 = tru[3 * n + 0];
    float t1 = tru[3 * n + 1];
    float t2 = tru[3 * n + 2];
    float ts = t0 + t1 + t2;

    // Packed broadcast constants (hoisted out of the loop)
    const u64 SS  = pk(s2, s2);
    const u64 LL0 = pk(l0, l0), LL1 = pk(l1, l1), LL2 = pk(l2, l2);
    const u64 L2E = pk(1.44269504089f, 1.44269504089f);
    const u64 K8 = pk(2.81022636e-08f, 2.81022636e-08f);
    const u64 K7 = pk(3.43273939e-07f, 3.43273939e-07f);
    const u64 K6 = pk(-3.5233877e-06f, -3.5233877e-06f);
    const u64 K5 = pk(-4.39150654e-06f, -4.39150654e-06f);
    const u64 K4 = pk(0.00021858087f, 0.00021858087f);
    const u64 K3 = pk(-0.00125372503f, -0.00125372503f);
    const u64 K2 = pk(-0.00417768164f, -0.00417768164f);
    const u64 K1 = pk(0.246640727f, 0.246640727f);
    const u64 K0 = pk(1.50140941f, 1.50140941f);

    const unsigned half   = (unsigned)N * 750u;
    const unsigned stride = (unsigned)N * 3u;
    unsigned base = ((unsigned)tb * (unsigned)N + (unsigned)n) * 3u;

    float acc_lz = 0.0f;             // sum of lg2(Z) over samples
    u64 ae0 = 0ull, ae1 = 0ull, ae2 = 0ull;  // packed sums of (p*x) per class

#pragma unroll 1
    for (int k = 0; k < TT; k++) {
        u64 E[3];
        float xA[3], xB[3], wA[3], wB[3];
        float maxwp = -1e30f;

#pragma unroll
        for (int c = 0; c < 3; c++) {
            unsigned b0, b1;
            tf2x32_k0(k1, ks2, k1p3, ks2p1, ks2p4,
                      base + (unsigned)c, half + base + (unsigned)c, b0, b1);
            float x0 = bits_to_x(b0);
            float x1 = bits_to_x(b1);
            // w' = w - 2.5 = -ln2*lg2(1-x^2) - 2.5 (one fma per normal)
            float lgA = lg2f(fmaf(-x0, x0, 1.0f));
            float lgB = lg2f(fmaf(-x1, x1, 1.0f));
            float wpA = fmaf(lgA, -0.6931471805599453f, -2.5f);
            float wpB = fmaf(lgB, -0.6931471805599453f, -2.5f);
            maxwp = fmaxf(maxwp, fmaxf(wpA, wpB));

            // Packed Horner (common branch of erf_inv)
            u64 W = pk(wpA, wpB);
            u64 q = fma2(K8, W, K7);
            q = fma2(q, W, K6);
            q = fma2(q, W, K5);
            q = fma2(q, W, K4);
            q = fma2(q, W, K3);
            q = fma2(q, W, K2);
            q = fma2(q, W, K1);
            q = fma2(q, W, K0);
            E[c] = mul2(q, pk(x0, x1));           // p*x (eps without sqrt2)

            xA[c] = x0; xB[c] = x1; wA[c] = wpA; wB[c] = wpB;
        }

        // Rare tail fixup: w >= 5  <=>  w' >= 2.5  (P ≈ 0.34% per normal)
        if (maxwp >= 2.5f) {
#pragma unroll
            for (int c = 0; c < 3; c++) {
                float eA, eB; upk(E[c], eA, eB);
                if (wA[c] >= 2.5f) eA = erfinv_tail(wA[c]) * xA[c];
                if (wB[c] >= 2.5f) eB = erfinv_tail(wB[c]) * xB[c];
                E[c] = pk(eA, eB);
            }
        }

        // Packed noisy logits + exp-arg; CE via no-max log-sum-exp.
        u64 N0 = fma2(E[0], SS, LL0);
        u64 N1 = fma2(E[1], SS, LL1);
        u64 N2 = fma2(E[2], SS, LL2);
        ae0 = add2(ae0, E[0]);
        ae1 = add2(ae1, E[1]);
        ae2 = add2(ae2, E[2]);
        u64 A0 = mul2(N0, L2E);
        u64 A1 = mul2(N1, L2E);
        u64 A2 = mul2(N2, L2E);
        float a0A, a0B, a1A, a1B, a2A, a2B;
        upk(A0, a0A, a0B); upk(A1, a1A, a1B); upk(A2, a2A, a2B);
        float ZA = ex2f(a0A) + ex2f(a1A) + ex2f(a2A);
        float ZB = ex2f(a0B) + ex2f(a1B) + ex2f(a2B);
        acc_lz += lg2f(ZA) + lg2f(ZB);

        base += stride;
    }

    // Collapse: sum_CE = ts*ln2*acc_lz - sum_c t_c * (S*l_c + s2 * sum(p*x)_c)
    float e0l, e0h, e1l, e1h, e2l, e2h;
    upk(ae0, e0l, e0h); upk(ae1, e1l, e1h); upk(ae2, e2l, e2h);
    float S = (float)(2 * TT);
    float n0s = fmaf(s2, e0l + e0h, S * l0);
    float n1s = fmaf(s2, e1l + e1h, S * l1);
    float n2s = fmaf(s2, e2l + e2h, S * l2);
    return ts * (0.6931471805599453f * acc_lz)
           - (t0 * n0s + t1 * n1s + t2 * n2s);
}

// ---------------------------------------------------------------------------
// Single fused kernel: img blocks + cls blocks + last-block finalize.
// ---------------------------------------------------------------------------
__global__ __launch_bounds__(256)
void fused_mc_loss_kernel(const float* __restrict__ true_img,
                          const float4* __restrict__ pred_img,
                          const float* __restrict__ true_cls,
                          const float4* __restrict__ pred_cls,
                          const float* __restrict__ log_vars,
                          const float* __restrict__ w_img,
                          const float* __restrict__ w_cls,
                          float* __restrict__ out,
                          int Nimg, int Ncls, int Bimg) {
    int bid = blockIdx.x;
    float local;
    int accIdx;
    if (bid < Bimg) {
        int tid = bid * 256 + threadIdx.x;
        local = mc_work(true_img, pred_img, Nimg, 5, 50, tid, 123u);
        accIdx = 0;
    } else {
        int tid = (bid - Bimg) * 256 + threadIdx.x;
        local = mc_work(true_cls, pred_cls, Ncls, 1, 250, tid, 456u);
        accIdx = 1;
    }

    // Block reduction: warp shuffle -> shared -> one double atomic per block
#pragma unroll
    for (int o = 16; o > 0; o >>= 1)
        local += __shfl_down_sync(0xffffffffu, local, o);

    __shared__ float warpsum[8];
    int lane = threadIdx.x & 31;
    int w    = threadIdx.x >> 5;
    if (lane == 0) warpsum[w] = local;
    __syncthreads();
    if (threadIdx.x == 0) {
        float v = warpsum[0];
#pragma unroll
        for (int i = 1; i < 8; i++) v += warpsum[i];
        atomicAdd(&g_accum[accIdx], (double)v);

        __threadfence();
        unsigned ticket = atomicAdd(&g_done, 1u);
        if (ticket == (unsigned)(gridDim.x - 1)) {
            // Last block: finalize and reset state for the next replay.
            __threadfence();
            double li_d = g_accum[0] / (500.0 * (double)Nimg);
            double lc_d = g_accum[1] / (500.0 * (double)Ncls);
            float mwi = (w_img[0] + w_img[1] + w_img[2]) * (1.0f / 3.0f);
            float mwc = (w_cls[0] + w_cls[1] + w_cls[2]) * (1.0f / 3.0f);
            float li = (float)li_d * mwi;
            float lc = (float)lc_d * mwc;
            float lv0 = log_vars[0], lv1 = log_vars[1];
            out[0] = expf(-lv0) * li + lv0 + expf(-lv1) * lc + lv1;
            g_accum[0] = 0.0;
            g_accum[1] = 0.0;
            g_done = 0u;
        }
    }
}

// ---------------------------------------------------------------------------
// kernel_launch — ONE kernel, graph-capturable, allocation-free.
// Inputs: 0=true_img 1=pred_img 2=true_cls 3=pred_cls 4=log_vars 5=w_img 6=w_cls
// ---------------------------------------------------------------------------
extern "C" void kernel_launch(void* const* d_in, const int* in_sizes, int n_in,
                              void* d_out, int out_size) {
    (void)n_in; (void)out_size;
    const float* true_img = (const float*)d_in[0];
    const float* pred_img = (const float*)d_in[1];
    const float* true_cls = (const float*)d_in[2];
    const float* pred_cls = (const float*)d_in[3];
    const float* log_vars = (const float*)d_in[4];
    const float* w_img    = (const float*)d_in[5];
    const float* w_cls    = (const float*)d_in[6];

    int Nimg = in_sizes[1] / 4;   // 65536 pixels
    int Ncls = in_sizes[3] / 4;   // 4 rows

    int Bimg = (Nimg * 50 + 255) / 256;    // TT=5 -> 50 chunks/pixel
    int Bcls = (Ncls * 250 + 255) / 256;   // TT=1 -> 250 chunks/row

    fused_mc_loss_kernel<<<Bimg + Bcls, 256>>>(
        true_img, (const float4*)pred_img,
        true_cls, (const float4*)pred_cls,
        log_vars, w_img, w_cls, (float*)d_out,
        Nimg, Ncls, Bimg);
}

// round 6
// speedup vs baseline: 14.4461x; 7.3286x over previous
#include <cuda_runtime.h>

// ---------------------------------------------------------------------------
// Device-global state. Finalizing block resets it each launch.
// ---------------------------------------------------------------------------
__device__ double   g_accum[2];   // [0]=img CE sum, [1]=cls CE sum
__device__ unsigned g_done;

__device__ __forceinline__ float lg2f(float x) {
    float y; asm("lg2.approx.f32 %0,%1;" : "=f"(y) : "f"(x)); return y;
}
__device__ __forceinline__ float ex2f(float x) {
    float y; asm("ex2.approx.f32 %0,%1;" : "=f"(y) : "f"(x)); return y;
}

// ---------------------------------------------------------------------------
// JAX threefry-2x32, key=(0,k1); ks2 = k1 ^ 0x1BD11BDA. Exact port (with
// k0 = 0 folded out). Used ONLY for the tiny cls MC (1000 ciphers).
// ---------------------------------------------------------------------------
__device__ __forceinline__ void tf2x32_k0(unsigned k1, unsigned ks2,
                                          unsigned x0, unsigned x1,
                                          unsigned& o0, unsigned& o1) {
    /* inject ks[0]=0, ks[1]=k1 */
    x1 += k1;
#define TF_RND(R) { x0 += x1; x1 = __funnelshift_l(x1, x1, (R)); x1 ^= x0; }
    TF_RND(13) TF_RND(15) TF_RND(26) TF_RND(6)
    x0 += k1;  x1 += ks2 + 1u;
    TF_RND(17) TF_RND(29) TF_RND(16) TF_RND(24)
    x0 += ks2; x1 += 2u;                  /* k0 + 2 = 2 */
    TF_RND(13) TF_RND(15) TF_RND(26) TF_RND(6)
    /* x0 += k0 = 0 */ x1 += k1 + 3u;
    TF_RND(17) TF_RND(29) TF_RND(16) TF_RND(24)
    x0 += k1;  x1 += ks2 + 4u;
    TF_RND(13) TF_RND(15) TF_RND(26) TF_RND(6)
    x0 += ks2; x1 += 5u;                  /* k0 + 5 = 5 */
#undef TF_RND
    o0 = x0; o1 = x1;
}

// XLA ErfInv f32 (Giles), both branches — cls path only, cost irrelevant.
__device__ __forceinline__ float erfinv_xla(float x) {
    float w = -__logf(fmaf(-x, x, 1.0f));
    float p;
    if (w < 5.0f) {
        w = w - 2.5f;
        p = 2.81022636e-08f;
        p = fmaf(p, w, 3.43273939e-07f);
        p = fmaf(p, w, -3.5233877e-06f);
        p = fmaf(p, w, -4.39150654e-06f);
        p = fmaf(p, w, 0.00021858087f);
        p = fmaf(p, w, -0.00125372503f);
        p = fmaf(p, w, -0.00417768164f);
        p = fmaf(p, w, 0.246640727f);
        p = fmaf(p, w, 1.50140941f);
    } else {
        w = sqrtf(w) - 3.0f;
        p = -0.000200214257f;
        p = fmaf(p, w, 0.000100950558f);
        p = fmaf(p, w, 0.00134934322f);
        p = fmaf(p, w, -0.00367342844f);
        p = fmaf(p, w, 0.00573950773f);
        p = fmaf(p, w, -0.0076224613f);
        p = fmaf(p, w, 0.00943887047f);
        p = fmaf(p, w, 1.00167406f);
        p = fmaf(p, w, 2.83297682f);
    }
    return p * x;
}

__device__ __forceinline__ float bits_to_normal(unsigned b) {
    float u01 = __uint_as_float((b >> 9) | 0x3f800000u) - 1.0f;
    float x = fmaf(u01, 1.9999999403953552f, -0.99999994039535522f);
    x = fmaxf(x, -0.99999994039535522f);
    return 1.4142135381698608f * erfinv_xla(x);
}

__device__ __forceinline__ float ce3(float l0, float l1, float l2, float s,
                                     float e0, float e1, float e2,
                                     float t0, float t1, float t2, float ts) {
    float n0 = fmaf(e0, s, l0);
    float n1 = fmaf(e1, s, l1);
    float n2 = fmaf(e2, s, l2);
    float m  = fmaxf(n0, fmaxf(n1, n2));
    float s0 = n0 - m, s1 = n1 - m, s2 = n2 - m;
    float Z  = __expf(s0) + __expf(s1) + __expf(s2);
    float lZ = __logf(Z);
    return ts * lZ - (t0 * s0 + t1 * s1 + t2 * s2);
}

// Bit-matched MC for cls: thread tid handles (row n, t-pair (t, t+250)).
__device__ float cls_mc_work(const float* __restrict__ tru,
                             const float4* __restrict__ pred,
                             int N, int tid, unsigned k1) {
    int total = N * 250;
    if (tid >= total) return 0.0f;
    const unsigned ks2 = k1 ^ 0x1BD11BDAu;
    int n = tid / 250;
    int t = tid - n * 250;

    float4 p = pred[n];
    float l0 = p.x, l1 = p.y, l2 = p.z;
    float scale = sqrtf(__expf(p.w));
    float t0 = tru[3 * n + 0];
    float t1 = tru[3 * n + 1];
    float t2 = tru[3 * n + 2];
    float ts = t0 + t1 + t2;

    const unsigned half = (unsigned)N * 750u;
    unsigned base = ((unsigned)t * (unsigned)N + (unsigned)n) * 3u;

    float eA[3], eB[3];
#pragma unroll
    for (int c = 0; c < 3; c++) {
        unsigned b0, b1;
        tf2x32_k0(k1, ks2, base + (unsigned)c, half + base + (unsigned)c, b0, b1);
        eA[c] = bits_to_normal(b0);
        eB[c] = bits_to_normal(b1);
    }
    return ce3(l0, l1, l2, scale, eA[0], eA[1], eA[2], t0, t1, t2, ts)
         + ce3(l0, l1, l2, scale, eB[0], eB[1], eB[2], t0, t1, t2, ts);
}

// ---------------------------------------------------------------------------
// img path: exact E[CE] per pixel via 2-D midpoint-rule Gaussian quadrature.
//   E[CE] = ts*(l0 + ln2 * E[G]) - (t0*l0 + t1*l1 + t2*l2)
//   G = lg2(1 + 2^t1 + 2^t2),  t = (mu + s*L*u)*log2e,  u ~ N(0, I2)
//   L = [[sqrt2, 0], [1/sqrt2, sqrt(3/2)]]
// 8 threads per pixel split the outer (u1) loop; inner (u2) loop full.
// Nodes: u_i = -6 + (i+0.5)h, h = 12/n, n = clamp(ceil(9 s), 11, 96).
// Normalization: accg / (sw1 * sw2) where sw2 is computed with the SAME
// multiplicative recurrence as the inner weights (drift self-cancels).
// ---------------------------------------------------------------------------
__device__ float img_quad_work(const float* __restrict__ tru,
                               const float4* __restrict__ pred,
                               int Nimg, int gtid) {
    int pix = gtid >> 3;
    int sub = gtid & 7;
    int valid = (pix < Nimg);
    if (!valid) pix = 0;            // keep lanes alive for the shuffles

    float4 p = pred[pix];
    float l0 = p.x, l1 = p.y, l2 = p.z, z = p.w;
    float s = __expf(0.5f * z);     // sqrt(exp(log_var))

    int n = (int)ceilf(9.0f * s);
    n = max(n, 11);
    n = min(n, 96);
    float h  = 12.0f / (float)n;
    float u0 = fmaf(0.5f, h, -6.0f);

    const float L2E = 1.4426950408889634f;
    float m1  = (l1 - l0) * L2E;
    float m2  = (l2 - l0) * L2E;
    float a1  = s * (1.4142135623730951f * L2E);
    float a2  = s * (0.7071067811865476f * L2E);
    float a3  = s * (1.224744871391589f  * L2E);
    float a3h = a3 * h;
    float m2p = fmaf(a3, u0, m2);          // fold u2-start into t2 base

    const float NH = -0.5f * L2E;          // w = 2^(NH*u^2) = e^(-u^2/2)
    float w2s = ex2f(NH * u0 * u0);        // w2 at j=0
    float r20 = ex2f(-L2E * fmaf(h, u0, 0.5f * h * h));  // w ratio at j=0
    float rho = ex2f(-L2E * h * h);        // ratio-of-ratios (constant)

    // Inner-weight sum via the SAME recurrence (drift-consistent normalizer).
    float sw2 = 0.0f;
    {
        float w2 = w2s, r2 = r20;
        for (int j = 0; j < n; j++) { sw2 += w2; w2 *= r2; r2 *= rho; }
    }

    float accg = 0.0f, sw1 = 0.0f;

    for (int i = sub; i < n; i += 8) {
        float u1  = fmaf((float)i, h, u0);
        float w1  = ex2f(NH * u1 * u1);
        float t1v = fminf(fmaf(a1, u1, m1), 120.0f);
        float A   = 1.0f + ex2f(t1v);
        float t2  = fmaf(a2, u1, m2p);
        float w2  = w2s;
        float r2  = r20;
        float acc_in = 0.0f;

#pragma unroll 4
        for (int j = 0; j < n; j++) {
            float e2 = ex2f(fminf(t2, 120.0f));
            float G  = lg2f(A + e2);
            acc_in   = fmaf(w2, G, acc_in);
            t2 += a3h;
            w2 *= r2;
            r2 *= rho;
        }
        accg = fmaf(w1, acc_in, accg);
        sw1 += w1;
    }

    // Combine the 8 sub-threads of this pixel (aligned 8-lane groups).
#pragma unroll
    for (int o = 4; o > 0; o >>= 1) {
        accg += __shfl_down_sync(0xffffffffu, accg, o);
        sw1  += __shfl_down_sync(0xffffffffu, sw1, o);
    }

    float ce = 0.0f;
    if (sub == 0 && valid) {
        float t0 = tru[3 * pix + 0];
        float tc1 = tru[3 * pix + 1];
        float tc2 = tru[3 * pix + 2];
        float ts = t0 + tc1 + tc2;
        float meanLSE = fmaf(0.6931471805599453f, accg / (sw1 * sw2), l0);
        ce = ts * meanLSE - (t0 * l0 + tc1 * l1 + tc2 * l2);
    }
    return ce;
}

// ---------------------------------------------------------------------------
// Single fused kernel: img quadrature blocks + cls MC blocks + finalize.
// ---------------------------------------------------------------------------
__global__ __launch_bounds__(256)
void fused_loss_kernel(const float* __restrict__ true_img,
                       const float4* __restrict__ pred_img,
                       const float* __restrict__ true_cls,
                       const float4* __restrict__ pred_cls,
                       const float* __restrict__ log_vars,
                       const float* __restrict__ w_img,
                       const float* __restrict__ w_cls,
                       float* __restrict__ out,
                       int Nimg, int Ncls, int Bimg) {
    int bid = blockIdx.x;
    float local;
    int accIdx;
    if (bid < Bimg) {
        local = img_quad_work(true_img, pred_img, Nimg, bid * 256 + threadIdx.x);
        accIdx = 0;
    } else {
        local = cls_mc_work(true_cls, pred_cls, Ncls,
                            (bid - Bimg) * 256 + threadIdx.x, 456u);
        accIdx = 1;
    }

    // Block reduction
#pragma unroll
    for (int o = 16; o > 0; o >>= 1)
        local += __shfl_down_sync(0xffffffffu, local, o);

    __shared__ float warpsum[8];
    int lane = threadIdx.x & 31;
    int w    = threadIdx.x >> 5;
    if (lane == 0) warpsum[w] = local;
    __syncthreads();
    if (threadIdx.x == 0) {
        float v = warpsum[0];
#pragma unroll
        for (int i = 1; i < 8; i++) v += warpsum[i];
        atomicAdd(&g_accum[accIdx], (double)v);

        __threadfence();
        unsigned ticket = atomicAdd(&g_done, 1u);
        if (ticket == (unsigned)(gridDim.x - 1)) {
            __threadfence();
            double li_d = g_accum[0] / (double)Nimg;           // quadrature: /N only
            double lc_d = g_accum[1] / (500.0 * (double)Ncls); // MC: /(T*N)
            float mwi = (w_img[0] + w_img[1] + w_img[2]) * (1.0f / 3.0f);
            float mwc = (w_cls[0] + w_cls[1] + w_cls[2]) * (1.0f / 3.0f);
            float li = (float)li_d * mwi;
            float lc = (float)lc_d * mwc;
            float lv0 = log_vars[0], lv1 = log_vars[1];
            out[0] = expf(-lv0) * li + lv0 + expf(-lv1) * lc + lv1;
            g_accum[0] = 0.0;
            g_accum[1] = 0.0;
            g_done = 0u;
        }
    }
}

// ---------------------------------------------------------------------------
// kernel_launch — ONE kernel, graph-capturable, allocation-free.
// ---------------------------------------------------------------------------
extern "C" void kernel_launch(void* const* d_in, const int* in_sizes, int n_in,
                              void* d_out, int out_size) {
    (void)n_in; (void)out_size;
    const float* true_img = (const float*)d_in[0];
    const float* pred_img = (const float*)d_in[1];
    const float* true_cls = (const float*)d_in[2];
    const float* pred_cls = (const float*)d_in[3];
    const float* log_vars = (const float*)d_in[4];
    const float* w_img    = (const float*)d_in[5];
    const float* w_cls    = (const float*)d_in[6];

    int Nimg = in_sizes[1] / 4;   // 65536 pixels
    int Ncls = in_sizes[3] / 4;   // 4 rows

    int Bimg = (Nimg * 8 + 255) / 256;     // 8 threads per pixel
    int Bcls = (Ncls * 250 + 255) / 256;   // exact-MC path

    fused_loss_kernel<<<Bimg + Bcls, 256>>>(
        true_img, (const float4*)pred_img,
        true_cls, (const float4*)pred_cls,
        log_vars, w_img, w_cls, (float*)d_out,
        Nimg, Ncls, Bimg);
}